// round 2
// baseline (speedup 1.0000x reference)
#include <cuda_runtime.h>
#include <cstdint>

// ---------------------------------------------------------------------------
// NeuralSDEHead: batch=8, d_model=512, hidden=64, n_paths=4096, horizon=128
// out = [paths (8*4096*128), mu (8), sigma (8)]  all fp32
// PRNG: JAX threefry2x32, jax_threefry_partitionable=True semantics.
// ---------------------------------------------------------------------------

#define BATCH    8
#define DMODEL   512
#define HIDDEN   64
#define NPATHS   4096
#define HORIZON  128
#define BN       (BATCH * NPATHS)      /* 32768 */
#define PATHS_ELEMS (BN * HORIZON)     /* 4194304 */

// Scratch (allocation-free rule: __device__ globals)
__device__ float        g_base_f1[BATCH * HIDDEN];
__device__ float        g_base_g1[BATCH * HIDDEN];
__device__ unsigned int g_keys[2 * HORIZON];

// ---------------------------------------------------------------------------
// Threefry-2x32 (JAX-compatible, 20 rounds)
// ---------------------------------------------------------------------------
__device__ __forceinline__ void threefry2x32(unsigned int k0, unsigned int k1,
                                             unsigned int x0, unsigned int x1,
                                             unsigned int* o0, unsigned int* o1)
{
    unsigned int ks0 = k0, ks1 = k1, ks2 = k0 ^ k1 ^ 0x1BD11BDAu;
    x0 += ks0; x1 += ks1;
#define TF_ROUND(r) { x0 += x1; x1 = __funnelshift_l(x1, x1, (r)); x1 ^= x0; }
    TF_ROUND(13) TF_ROUND(15) TF_ROUND(26) TF_ROUND(6)
    x0 += ks1; x1 += ks2 + 1u;
    TF_ROUND(17) TF_ROUND(29) TF_ROUND(16) TF_ROUND(24)
    x0 += ks2; x1 += ks0 + 2u;
    TF_ROUND(13) TF_ROUND(15) TF_ROUND(26) TF_ROUND(6)
    x0 += ks0; x1 += ks1 + 3u;
    TF_ROUND(17) TF_ROUND(29) TF_ROUND(16) TF_ROUND(24)
    x0 += ks1; x1 += ks2 + 4u;
    TF_ROUND(13) TF_ROUND(15) TF_ROUND(26) TF_ROUND(6)
    x0 += ks2; x1 += ks0 + 5u;
#undef TF_ROUND
    *o0 = x0; *o1 = x1;
}

// XLA ErfInv32 (Giles polynomial) — matches jax.random.normal's erf_inv
__device__ __forceinline__ float erfinv_xla(float x)
{
    float w = -log1pf(-x * x);
    float p;
    if (w < 5.0f) {
        w = w - 2.5f;
        p = 2.81022636e-08f;
        p = fmaf(p, w, 3.43273939e-07f);
        p = fmaf(p, w, -3.5233877e-06f);
        p = fmaf(p, w, -4.39150654e-06f);
        p = fmaf(p, w, 0.00021858087f);
        p = fmaf(p, w, -0.00125372503f);
        p = fmaf(p, w, -0.00417768164f);
        p = fmaf(p, w, 0.246640727f);
        p = fmaf(p, w, 1.50140941f);
    } else {
        w = sqrtf(w) - 3.0f;
        p = -0.000200214257f;
        p = fmaf(p, w, 0.000100950558f);
        p = fmaf(p, w, 0.00134934322f);
        p = fmaf(p, w, -0.00367342844f);
        p = fmaf(p, w, 0.00573950773f);
        p = fmaf(p, w, -0.0076224613f);
        p = fmaf(p, w, 0.00943887047f);
        p = fmaf(p, w, 1.00167406f);
        p = fmaf(p, w, 2.83297682f);
    }
    return p * x;
}

__device__ __forceinline__ float silu_f(float x)
{
    return __fdividef(x, 1.0f + __expf(-x));
}

__device__ __forceinline__ float softplus_acc(float x)
{
    // jax.nn.softplus = logaddexp(x, 0) = max(x,0) + log1p(exp(-|x|))
    return fmaxf(x, 0.0f) + log1pf(__expf(-fabsf(x)));
}

// packed f32x2 helpers -------------------------------------------------------
__device__ __forceinline__ unsigned long long pack_dup(float x)
{
    unsigned int b = __float_as_uint(x);
    unsigned long long r;
    asm("mov.b64 %0, {%1, %2};" : "=l"(r) : "r"(b), "r"(b));
    return r;
}
__device__ __forceinline__ unsigned long long pack2(float lo, float hi)
{
    unsigned int a = __float_as_uint(lo), b = __float_as_uint(hi);
    unsigned long long r;
    asm("mov.b64 %0, {%1, %2};" : "=l"(r) : "r"(a), "r"(b));
    return r;
}
__device__ __forceinline__ float2 unpack2(unsigned long long v)
{
    unsigned int lo, hi;
    asm("mov.b64 {%0, %1}, %2;" : "=r"(lo), "=r"(hi) : "l"(v));
    return make_float2(__uint_as_float(lo), __uint_as_float(hi));
}
#define FMA2(acc, a, b) asm("fma.rn.f32x2 %0, %1, %2, %0;" : "+l"(acc) : "l"(a), "l"(b))

// ---------------------------------------------------------------------------
// Setup kernel 1: partitionable (fold-like) split:
//   key[j] = threefry2x32(key=(0,42), counts=(hi=0, lo=j))  ->  (o0, o1)
// ---------------------------------------------------------------------------
__global__ void keys_kernel()
{
    unsigned int j = threadIdx.x;   // 0..127
    unsigned int o0, o1;
    threefry2x32(0u, 42u, 0u, j, &o0, &o1);
    g_keys[2 * j]     = o0;
    g_keys[2 * j + 1] = o1;
}

// ---------------------------------------------------------------------------
// Setup kernel 2 (grid=8, block=160): per-batch bases + mu/sigma
// ---------------------------------------------------------------------------
__global__ void precompute_kernel(const float* __restrict__ h_t,
                                  const float* __restrict__ W_f1, const float* __restrict__ b_f1,
                                  const float* __restrict__ W_g1, const float* __restrict__ b_g1,
                                  const float* __restrict__ W_mu, const float* __restrict__ b_mu,
                                  const float* __restrict__ W_sig, const float* __restrict__ b_sig,
                                  float* __restrict__ out_mu, float* __restrict__ out_sigma)
{
    int b = blockIdx.x;
    int tid = threadIdx.x;
    const float* h = h_t + b * DMODEL;
    if (tid < HIDDEN) {
        float s = b_f1[tid];
        for (int i = 0; i < DMODEL; ++i)
            s = fmaf(h[i], W_f1[i * HIDDEN + tid], s);
        g_base_f1[b * HIDDEN + tid] = s;
    } else if (tid < 2 * HIDDEN) {
        int j = tid - HIDDEN;
        float s = b_g1[j];
        for (int i = 0; i < DMODEL; ++i)
            s = fmaf(h[i], W_g1[i * HIDDEN + j], s);
        g_base_g1[b * HIDDEN + j] = s;
    } else if (tid == 2 * HIDDEN) {
        float s = b_mu[0];
        for (int i = 0; i < DMODEL; ++i) s = fmaf(h[i], W_mu[i], s);
        out_mu[b] = s;
    } else if (tid == 2 * HIDDEN + 1) {
        float s = b_sig[0];
        for (int i = 0; i < DMODEL; ++i) s = fmaf(h[i], W_sig[i], s);
        out_sigma[b] = fmaxf(s, 0.0f) + log1pf(expf(-fabsf(s))) + 1e-6f;
    }
}

// ---------------------------------------------------------------------------
// Main kernel: one thread per (batch,path) row, 128 sequential Euler steps.
// grid = 128 blocks x 256 threads; every block maps to a single batch index.
// ---------------------------------------------------------------------------
__global__ __launch_bounds__(256, 1)
void sde_main_kernel(const float* __restrict__ W_f1,
                     const float* __restrict__ W_f2, const float* __restrict__ b_f2,
                     const float* __restrict__ W_f3, const float* __restrict__ b_f3,
                     const float* __restrict__ W_g1,
                     const float* __restrict__ W_g2, const float* __restrict__ b_g2,
                     const float* __restrict__ initial_price,
                     float* __restrict__ out_paths)
{
    __shared__ __align__(16) float sWf2[HIDDEN * HIDDEN];   // 16 KB
    __shared__ __align__(16) float sbf2[HIDDEN];
    __shared__ float sWf3[HIDDEN], sWg2[HIDDEN];
    __shared__ float sbase_f1[HIDDEN], swy_f1[HIDDEN], swt_f1[HIDDEN];
    __shared__ float sbase_g1[HIDDEN], swy_g1[HIDDEN], swt_g1[HIDDEN];
    __shared__ unsigned int skeys[2 * HORIZON];

    const int tid = threadIdx.x;
    const int row = blockIdx.x * 256 + tid;
    const int b   = row >> 12;                    // 4096 rows per batch; uniform per block

    for (int i = tid; i < HIDDEN * HIDDEN; i += 256) sWf2[i] = W_f2[i];
    if (tid < HIDDEN) {
        sbf2[tid]     = b_f2[tid];
        sWf3[tid]     = W_f3[tid];
        sWg2[tid]     = W_g2[tid];
        sbase_f1[tid] = g_base_f1[b * HIDDEN + tid];
        sbase_g1[tid] = g_base_g1[b * HIDDEN + tid];
        swy_f1[tid]   = W_f1[512 * HIDDEN + tid];
        swt_f1[tid]   = W_f1[513 * HIDDEN + tid];
        swy_g1[tid]   = W_g1[512 * HIDDEN + tid];
        swt_g1[tid]   = W_g1[513 * HIDDEN + tid];
    }
    skeys[tid] = g_keys[tid];   // 256 threads, 256 uints
    __syncthreads();

    const float bf3v = b_f3[0];
    const float bg2v = b_g2[0];

    float y = logf(initial_price[b]);

    const unsigned int cnt_lo = (unsigned int)row;   // iota_2x32: hi=0, lo=flat index
    float* outp = out_paths + (size_t)row * HORIZON;

    #pragma unroll 1
    for (int step = 0; step < HORIZON; ++step) {
        const float t = (float)step;

        // ---- noise: partitionable random_bits = o0 ^ o1, counts=(0,row) ----
        unsigned int o0, o1;
        threefry2x32(skeys[2 * step], skeys[2 * step + 1], 0u, cnt_lo, &o0, &o1);
        const unsigned int bits = o0 ^ o1;
        const float u01 = __uint_as_float((bits >> 9) | 0x3f800000u) - 1.0f;
        float u = fmaf(u01, 2.0f, -0.99999994039535522f);  // span rounds to 2.0f exactly
        u = fmaxf(-0.99999994039535522f, u);
        const float z = 1.4142135381698608f * erfinv_xla(u);

        // ---- h1 = silu(base_f1 + y*wy + t*wt) ----
        float h1[HIDDEN];
        #pragma unroll
        for (int i = 0; i < HIDDEN; ++i) {
            float x = fmaf(y, swy_f1[i], fmaf(t, swt_f1[i], sbase_f1[i]));
            h1[i] = silu_f(x);
        }

        // ---- h2_pre = h1 @ W_f2 + b_f2  (packed f32x2 FMA) ----
        unsigned long long acc[HIDDEN / 2];
        #pragma unroll
        for (int m = 0; m < HIDDEN / 2; ++m) {
            float2 bb = *reinterpret_cast<const float2*>(&sbf2[2 * m]);
            acc[m] = pack2(bb.x, bb.y);
        }
        #pragma unroll
        for (int i = 0; i < HIDDEN; ++i) {
            const unsigned long long a2 = pack_dup(h1[i]);
            const ulonglong2* wr = reinterpret_cast<const ulonglong2*>(&sWf2[i * HIDDEN]);
            #pragma unroll
            for (int q = 0; q < HIDDEN / 4; ++q) {
                ulonglong2 w = wr[q];                     // 4 floats (cols 4q..4q+3)
                FMA2(acc[2 * q],     a2, w.x);
                FMA2(acc[2 * q + 1], a2, w.y);
            }
        }

        // ---- f = silu(h2_pre) @ W_f3 + b_f3 ----
        float f = bf3v;
        #pragma unroll
        for (int m = 0; m < HIDDEN / 2; ++m) {
            float2 h2 = unpack2(acc[m]);
            f = fmaf(silu_f(h2.x), sWf3[2 * m],     f);
            f = fmaf(silu_f(h2.y), sWf3[2 * m + 1], f);
        }

        // ---- g = softplus(silu(base_g1 + y*wy + t*wt) @ W_g2 + b_g2) + 1e-6 ----
        float ga = bg2v;
        #pragma unroll
        for (int i = 0; i < HIDDEN; ++i) {
            float x = fmaf(y, swy_g1[i], fmaf(t, swt_g1[i], sbase_g1[i]));
            ga = fmaf(silu_f(x), sWg2[i], ga);
        }
        const float g = softplus_acc(ga) + 1e-6f;

        // ---- Euler-Maruyama (dt = 1, sqrt_dt = 1) ----
        y = (y + f) + g * z;

        const float yc = fminf(fmaxf(y, -20.0f), 20.0f);
        outp[step] = __expf(yc);
    }
}

// ---------------------------------------------------------------------------
// Launch (graph-capturable: kernels only, no allocs/syncs)
// ---------------------------------------------------------------------------
extern "C" void kernel_launch(void* const* d_in, const int* in_sizes, int n_in,
                              void* d_out, int out_size)
{
    const float* h_t    = (const float*)d_in[0];
    const float* price  = (const float*)d_in[1];
    const float* W_f1   = (const float*)d_in[2];
    const float* b_f1   = (const float*)d_in[3];
    const float* W_f2   = (const float*)d_in[4];
    const float* b_f2   = (const float*)d_in[5];
    const float* W_f3   = (const float*)d_in[6];
    const float* b_f3   = (const float*)d_in[7];
    const float* W_g1   = (const float*)d_in[8];
    const float* b_g1   = (const float*)d_in[9];
    const float* W_g2   = (const float*)d_in[10];
    const float* b_g2   = (const float*)d_in[11];
    const float* W_mu   = (const float*)d_in[12];
    const float* b_mu   = (const float*)d_in[13];
    const float* W_sig  = (const float*)d_in[14];
    const float* b_sig  = (const float*)d_in[15];

    float* out        = (float*)d_out;
    float* out_paths  = out;
    float* out_mu     = out + PATHS_ELEMS;
    float* out_sigma  = out + PATHS_ELEMS + BATCH;

    keys_kernel<<<1, 128>>>();
    precompute_kernel<<<BATCH, 160>>>(h_t, W_f1, b_f1, W_g1, b_g1,
                                      W_mu, b_mu, W_sig, b_sig,
                                      out_mu, out_sigma);
    sde_main_kernel<<<BN / 256, 256>>>(W_f1, W_f2, b_f2, W_f3, b_f3,
                                       W_g1, W_g2, b_g2, price, out_paths);
}

// round 6
// speedup vs baseline: 1.0631x; 1.0631x over previous
#include <cuda_runtime.h>
#include <cstdint>

// ---------------------------------------------------------------------------
// NeuralSDEHead: batch=8, d_model=512, hidden=64, n_paths=4096, horizon=128
// out = [paths (8*4096*128), mu (8), sigma (8)]  all fp32
// PRNG: JAX threefry2x32, jax_threefry_partitionable=True semantics.
// Structure identical to the verified-passing Round-2 kernel; only the inner
// step loop is restructured (fused h1, unroll 4, partial sum chains).
// ---------------------------------------------------------------------------

#define BATCH    8
#define DMODEL   512
#define HIDDEN   64
#define NPATHS   4096
#define HORIZON  128
#define BN       (BATCH * NPATHS)      /* 32768 */
#define PATHS_ELEMS (BN * HORIZON)     /* 4194304 */

typedef unsigned long long ull;

// Scratch (allocation-free rule: __device__ globals)
__device__ float        g_base_f1[BATCH * HIDDEN];
__device__ float        g_base_g1[BATCH * HIDDEN];
__device__ unsigned int g_keys[2 * HORIZON];

// ---------------------------------------------------------------------------
// Threefry-2x32 (JAX-compatible, 20 rounds)
// ---------------------------------------------------------------------------
__device__ __forceinline__ void threefry2x32(unsigned int k0, unsigned int k1,
                                             unsigned int x0, unsigned int x1,
                                             unsigned int* o0, unsigned int* o1)
{
    unsigned int ks0 = k0, ks1 = k1, ks2 = k0 ^ k1 ^ 0x1BD11BDAu;
    x0 += ks0; x1 += ks1;
#define TF_ROUND(r) { x0 += x1; x1 = __funnelshift_l(x1, x1, (r)); x1 ^= x0; }
    TF_ROUND(13) TF_ROUND(15) TF_ROUND(26) TF_ROUND(6)
    x0 += ks1; x1 += ks2 + 1u;
    TF_ROUND(17) TF_ROUND(29) TF_ROUND(16) TF_ROUND(24)
    x0 += ks2; x1 += ks0 + 2u;
    TF_ROUND(13) TF_ROUND(15) TF_ROUND(26) TF_ROUND(6)
    x0 += ks0; x1 += ks1 + 3u;
    TF_ROUND(17) TF_ROUND(29) TF_ROUND(16) TF_ROUND(24)
    x0 += ks1; x1 += ks2 + 4u;
    TF_ROUND(13) TF_ROUND(15) TF_ROUND(26) TF_ROUND(6)
    x0 += ks2; x1 += ks0 + 5u;
#undef TF_ROUND
    *o0 = x0; *o1 = x1;
}

// XLA ErfInv32 (Giles polynomial)
__device__ __forceinline__ float erfinv_xla(float x)
{
    float w = -log1pf(-x * x);
    float p;
    if (w < 5.0f) {
        w = w - 2.5f;
        p = 2.81022636e-08f;
        p = fmaf(p, w, 3.43273939e-07f);
        p = fmaf(p, w, -3.5233877e-06f);
        p = fmaf(p, w, -4.39150654e-06f);
        p = fmaf(p, w, 0.00021858087f);
        p = fmaf(p, w, -0.00125372503f);
        p = fmaf(p, w, -0.00417768164f);
        p = fmaf(p, w, 0.246640727f);
        p = fmaf(p, w, 1.50140941f);
    } else {
        w = sqrtf(w) - 3.0f;
        p = -0.000200214257f;
        p = fmaf(p, w, 0.000100950558f);
        p = fmaf(p, w, 0.00134934322f);
        p = fmaf(p, w, -0.00367342844f);
        p = fmaf(p, w, 0.00573950773f);
        p = fmaf(p, w, -0.0076224613f);
        p = fmaf(p, w, 0.00943887047f);
        p = fmaf(p, w, 1.00167406f);
        p = fmaf(p, w, 2.83297682f);
    }
    return p * x;
}

__device__ __forceinline__ float silu_f(float x)
{
    return __fdividef(x, 1.0f + __expf(-x));
}

__device__ __forceinline__ float softplus_acc(float x)
{
    return fmaxf(x, 0.0f) + log1pf(__expf(-fabsf(x)));
}

// packed f32x2 helpers -------------------------------------------------------
__device__ __forceinline__ ull pack_dup(float x)
{
    unsigned int b = __float_as_uint(x);
    ull r;
    asm("mov.b64 %0, {%1, %2};" : "=l"(r) : "r"(b), "r"(b));
    return r;
}
__device__ __forceinline__ ull pack2(float lo, float hi)
{
    unsigned int a = __float_as_uint(lo), b = __float_as_uint(hi);
    ull r;
    asm("mov.b64 %0, {%1, %2};" : "=l"(r) : "r"(a), "r"(b));
    return r;
}
__device__ __forceinline__ float2 unpack2(ull v)
{
    unsigned int lo, hi;
    asm("mov.b64 {%0, %1}, %2;" : "=r"(lo), "=r"(hi) : "l"(v));
    return make_float2(__uint_as_float(lo), __uint_as_float(hi));
}
#define FMA2(acc, a, b) asm("fma.rn.f32x2 %0, %1, %2, %0;" : "+l"(acc) : "l"(a), "l"(b))

// ---------------------------------------------------------------------------
// Setup kernel 1: partitionable (fold-like) split:
//   key[j] = threefry2x32(key=(0,42), counts=(hi=0, lo=j))  ->  (o0, o1)
// ---------------------------------------------------------------------------
__global__ void keys_kernel()
{
    unsigned int j = threadIdx.x;   // 0..127
    unsigned int o0, o1;
    threefry2x32(0u, 42u, 0u, j, &o0, &o1);
    g_keys[2 * j]     = o0;
    g_keys[2 * j + 1] = o1;
}

// ---------------------------------------------------------------------------
// Setup kernel 2 (grid=8, block=160): per-batch bases + mu/sigma
// ---------------------------------------------------------------------------
__global__ void precompute_kernel(const float* __restrict__ h_t,
                                  const float* __restrict__ W_f1, const float* __restrict__ b_f1,
                                  const float* __restrict__ W_g1, const float* __restrict__ b_g1,
                                  const float* __restrict__ W_mu, const float* __restrict__ b_mu,
                                  const float* __restrict__ W_sig, const float* __restrict__ b_sig,
                                  float* __restrict__ out_mu, float* __restrict__ out_sigma)
{
    int b = blockIdx.x;
    int tid = threadIdx.x;
    const float* h = h_t + b * DMODEL;
    if (tid < HIDDEN) {
        float s = b_f1[tid];
        for (int i = 0; i < DMODEL; ++i)
            s = fmaf(h[i], W_f1[i * HIDDEN + tid], s);
        g_base_f1[b * HIDDEN + tid] = s;
    } else if (tid < 2 * HIDDEN) {
        int j = tid - HIDDEN;
        float s = b_g1[j];
        for (int i = 0; i < DMODEL; ++i)
            s = fmaf(h[i], W_g1[i * HIDDEN + j], s);
        g_base_g1[b * HIDDEN + j] = s;
    } else if (tid == 2 * HIDDEN) {
        float s = b_mu[0];
        for (int i = 0; i < DMODEL; ++i) s = fmaf(h[i], W_mu[i], s);
        out_mu[b] = s;
    } else if (tid == 2 * HIDDEN + 1) {
        float s = b_sig[0];
        for (int i = 0; i < DMODEL; ++i) s = fmaf(h[i], W_sig[i], s);
        out_sigma[b] = fmaxf(s, 0.0f) + log1pf(expf(-fabsf(s))) + 1e-6f;
    }
}

// ---------------------------------------------------------------------------
// Main kernel: one thread per (batch,path) row, 128 sequential Euler steps.
// grid = 128 blocks x 256 threads; every block maps to a single batch index.
// ---------------------------------------------------------------------------
__global__ __launch_bounds__(256, 1)
void sde_main_kernel(const float* __restrict__ W_f1,
                     const float* __restrict__ W_f2, const float* __restrict__ b_f2,
                     const float* __restrict__ W_f3, const float* __restrict__ b_f3,
                     const float* __restrict__ W_g1,
                     const float* __restrict__ W_g2, const float* __restrict__ b_g2,
                     const float* __restrict__ initial_price,
                     float* __restrict__ out_paths)
{
    __shared__ __align__(16) float sWf2[HIDDEN * HIDDEN];   // 16 KB
    __shared__ __align__(16) float sbf2[HIDDEN];
    __shared__ float sWf3[HIDDEN], sWg2[HIDDEN];
    __shared__ float sbase_f1[HIDDEN], swy_f1[HIDDEN], swt_f1[HIDDEN];
    __shared__ float sbase_g1[HIDDEN], swy_g1[HIDDEN], swt_g1[HIDDEN];
    __shared__ unsigned int skeys[2 * HORIZON];

    const int tid = threadIdx.x;
    const int row = blockIdx.x * 256 + tid;
    const int b   = row >> 12;                    // 4096 rows per batch; uniform per block

    for (int i = tid; i < HIDDEN * HIDDEN; i += 256) sWf2[i] = W_f2[i];
    if (tid < HIDDEN) {
        sbf2[tid]     = b_f2[tid];
        sWf3[tid]     = W_f3[tid];
        sWg2[tid]     = W_g2[tid];
        sbase_f1[tid] = g_base_f1[b * HIDDEN + tid];
        sbase_g1[tid] = g_base_g1[b * HIDDEN + tid];
        swy_f1[tid]   = W_f1[512 * HIDDEN + tid];
        swt_f1[tid]   = W_f1[513 * HIDDEN + tid];
        swy_g1[tid]   = W_g1[512 * HIDDEN + tid];
        swt_g1[tid]   = W_g1[513 * HIDDEN + tid];
    }
    skeys[tid] = g_keys[tid];   // 256 threads, 256 uints
    __syncthreads();

    const float bf3v = b_f3[0];
    const float bg2v = b_g2[0];

    float y = logf(initial_price[b]);

    const unsigned int cnt_lo = (unsigned int)row;   // iota_2x32: hi=0, lo=flat index
    float* outp = out_paths + (size_t)row * HORIZON;

    #pragma unroll 1
    for (int step = 0; step < HORIZON; ++step) {
        const float t = (float)step;

        // ---- noise: partitionable random_bits = o0 ^ o1, counts=(0,row) ----
        unsigned int o0, o1;
        threefry2x32(skeys[2 * step], skeys[2 * step + 1], 0u, cnt_lo, &o0, &o1);
        const unsigned int bits = o0 ^ o1;
        const float u01 = __uint_as_float((bits >> 9) | 0x3f800000u) - 1.0f;
        float u = fmaf(u01, 2.0f, -0.99999994039535522f);
        u = fmaxf(-0.99999994039535522f, u);
        const float z = 1.4142135381698608f * erfinv_xla(u);

        // ---- fused: h1 on the fly + h2_pre accumulation + g-branch dot ----
        ull acc[HIDDEN / 2];
        #pragma unroll
        for (int m = 0; m < HIDDEN / 2; ++m) {
            acc[m] = pack2(sbf2[2 * m], sbf2[2 * m + 1]);
        }
        float ga0 = bg2v, ga1 = 0.0f, ga2 = 0.0f, ga3 = 0.0f;

        #pragma unroll 4
        for (int i = 0; i < HIDDEN; ++i) {
            // f-branch pre-activation + silu (no h1[] array: consumed here)
            const float xf = fmaf(y, swy_f1[i], fmaf(t, swt_f1[i], sbase_f1[i]));
            const float hf = silu_f(xf);
            // g-branch pre-activation + silu + dot (4 partial chains)
            const float xg = fmaf(y, swy_g1[i], fmaf(t, swt_g1[i], sbase_g1[i]));
            const float hg = silu_f(xg);
            const float gw = sWg2[i];
            if      ((i & 3) == 0) ga0 = fmaf(hg, gw, ga0);
            else if ((i & 3) == 1) ga1 = fmaf(hg, gw, ga1);
            else if ((i & 3) == 2) ga2 = fmaf(hg, gw, ga2);
            else                   ga3 = fmaf(hg, gw, ga3);

            // f-branch matvec row i (packed f32x2, shared-broadcast weights)
            const ull a2 = pack_dup(hf);
            const ulonglong2* wr = reinterpret_cast<const ulonglong2*>(&sWf2[i * HIDDEN]);
            #pragma unroll
            for (int q = 0; q < HIDDEN / 4; ++q) {
                ulonglong2 w = wr[q];
                FMA2(acc[2 * q],     a2, w.x);
                FMA2(acc[2 * q + 1], a2, w.y);
            }
        }

        // ---- f = silu(h2_pre) @ W_f3 + b_f3 (2 partial chains) ----
        float f0 = bf3v, f1 = 0.0f;
        #pragma unroll
        for (int m = 0; m < HIDDEN / 2; ++m) {
            float2 h2 = unpack2(acc[m]);
            f0 = fmaf(silu_f(h2.x), sWf3[2 * m],     f0);
            f1 = fmaf(silu_f(h2.y), sWf3[2 * m + 1], f1);
        }
        const float f = f0 + f1;

        const float ga = (ga0 + ga1) + (ga2 + ga3);
        const float g = softplus_acc(ga) + 1e-6f;

        // ---- Euler-Maruyama (dt = 1, sqrt_dt = 1) ----
        y = (y + f) + g * z;

        const float yc = fminf(fmaxf(y, -20.0f), 20.0f);
        outp[step] = __expf(yc);
    }
}

// ---------------------------------------------------------------------------
// Launch (graph-capturable: kernels only, no allocs/syncs)
// ---------------------------------------------------------------------------
extern "C" void kernel_launch(void* const* d_in, const int* in_sizes, int n_in,
                              void* d_out, int out_size)
{
    const float* h_t    = (const float*)d_in[0];
    const float* price  = (const float*)d_in[1];
    const float* W_f1   = (const float*)d_in[2];
    const float* b_f1   = (const float*)d_in[3];
    const float* W_f2   = (const float*)d_in[4];
    const float* b_f2   = (const float*)d_in[5];
    const float* W_f3   = (const float*)d_in[6];
    const float* b_f3   = (const float*)d_in[7];
    const float* W_g1   = (const float*)d_in[8];
    const float* b_g1   = (const float*)d_in[9];
    const float* W_g2   = (const float*)d_in[10];
    const float* b_g2   = (const float*)d_in[11];
    const float* W_mu   = (const float*)d_in[12];
    const float* b_mu   = (const float*)d_in[13];
    const float* W_sig  = (const float*)d_in[14];
    const float* b_sig  = (const float*)d_in[15];

    float* out        = (float*)d_out;
    float* out_paths  = out;
    float* out_mu     = out + PATHS_ELEMS;
    float* out_sigma  = out + PATHS_ELEMS + BATCH;

    keys_kernel<<<1, 128>>>();
    precompute_kernel<<<BATCH, 160>>>(h_t, W_f1, b_f1, W_g1, b_g1,
                                      W_mu, b_mu, W_sig, b_sig,
                                      out_mu, out_sigma);
    sde_main_kernel<<<BN / 256, 256>>>(W_f1, W_f2, b_f2, W_f3, b_f3,
                                       W_g1, W_g2, b_g2, price, out_paths);
}